// round 16
// baseline (speedup 1.0000x reference)
#include <cuda_runtime.h>
#include <cuda_bf16.h>
#include <stdint.h>
#include <math.h>

// ---------------- problem constants ----------------
#define Nn    10000
#define Ee    160000
#define ETOT  170000          // edges + self loops
#define DIN   256
#define F1    512             // H*C1
#define C1    256
#define F2    1024            // H*C2
#define C2    512
#define HID   128
#define NOUT  3

#define NX   (Nn * DIN)       // 2,560,000
#define NW1  (DIN * F1)       // 131,072
#define NW2  (F1 * F2)        // 524,288
#define NWF  (F2 * HID)       // 131,072

// ---------------- device scratch (static, no allocs) ----------------
__device__ float  g_xs1[(size_t)Nn * F1];
__device__ float  g_h1 [(size_t)Nn * F1];    // PACKED pair layout (GEMM A)
__device__ float  g_xs2[(size_t)Nn * F2];    // also reused as gemm3 split-K partials
__device__ float  g_h2 [(size_t)Nn * F2];    // PACKED pair layout (GEMM A)
__device__ float  g_z  [(size_t)Nn * HID];
__device__ float  g_xtf[NX];             // tf32-rounded x, PACKED
__device__ float  g_w1tf[NW1];           // tf32-rounded w1s, TRANSPOSED+PACKED [F1][DIN]
__device__ float  g_w2tf[NW2];           // tf32-rounded w2s, TRANSPOSED+PACKED [F2][F1]
__device__ float  g_wftf[NWF];           // tf32-rounded wf1, TRANSPOSED+PACKED [HID][F2]
__device__ float4 g_asd1[Nn];            // (a_s h0, a_s h1, a_d h0, a_d h1)
__device__ float4 g_asd2[Nn];
__device__ float2 g_alpha[ETOT];         // per-slot e then unnormalized alpha
__device__ float2 g_invd[Nn];            // 1/denom per head
__device__ int    g_cnt[Nn];
__device__ int    g_off[Nn + 1];
__device__ int    g_cur[Nn];
__device__ int    g_ssrc[ETOT];          // CSR (grouped by dst): src node per slot
__device__ float4 g_v1[DIN];             // folded attention vectors layer1
__device__ float4 g_v2[F1];              // folded attention vectors layer2 (packed order)
__device__ float  g_sum[HID], g_ss[HID], g_mean[HID], g_rstd[HID];

__device__ __forceinline__ unsigned f2tf32(float f) {
    unsigned u;
    asm("cvt.rna.tf32.f32 %0, %1;" : "=r"(u) : "f"(f));
    return u;
}
__device__ __forceinline__ float f2tf32f(float f) {
    return __uint_as_float(f2tf32(f));
}

// packed pair layout: within each 8-k block, word w (0..7) holds original
// element k = 8*kb + (w>>1) + 4*(w&1)  — i.e. pairs (k, k+4) are adjacent.
__device__ __forceinline__ int pk_src(int rem) {
    int kb = rem >> 3, w = rem & 7;
    return (kb << 3) + (w >> 1) + ((w & 1) << 2);
}

// one-shot round + pack of all static GEMM operands
__global__ void round_all(const float* __restrict__ x, const float* __restrict__ w1s,
                          const float* __restrict__ w2s, const float* __restrict__ wf1) {
    int i = blockIdx.x * blockDim.x + threadIdx.x;
    if (i < NX) {
        int r = i / DIN, k = pk_src(i % DIN);
        g_xtf[i] = f2tf32f(x[r * DIN + k]);
        return;
    }
    i -= NX;
    if (i < NW1) {           // [F1][DIN] transposed+packed
        int n = i / DIN, k = pk_src(i % DIN);
        g_w1tf[i] = f2tf32f(w1s[k * F1 + n]);
        return;
    }
    i -= NW1;
    if (i < NW2) {           // [F2][F1]
        int n = i / F1, k = pk_src(i % F1);
        g_w2tf[i] = f2tf32f(w2s[k * F2 + n]);
        return;
    }
    i -= NW2;
    if (i < NWF) {           // [HID][F2]
        int n = i / F2, k = pk_src(i % F2);
        g_wftf[i] = f2tf32f(wf1[k * HID + n]);
        return;
    }
}

// ---------------- small utility kernels ----------------
__global__ void zero_k() {
    int i = blockIdx.x * blockDim.x + threadIdx.x;
    if (i < Nn) g_cnt[i] = 0;
    if (i < HID) { g_sum[i] = 0.f; g_ss[i] = 0.f; }
}

__global__ void count_k(const int* __restrict__ ei) {
    int i = blockIdx.x * blockDim.x + threadIdx.x;
    if (i >= ETOT) return;
    int d = (i < Ee) ? ei[Ee + i] : (i - Ee);
    atomicAdd(&g_cnt[d], 1);
}

// single block exclusive scan over g_cnt -> g_off (+ g_cur copy), 1024 threads
__global__ void scan_k() {
    __shared__ int part[1024];
    const int CH = 10;                       // 1024*10 >= Nn
    int t = threadIdx.x;
    int base = t * CH;
    int local[CH];
    int s = 0;
    #pragma unroll
    for (int j = 0; j < CH; j++) {
        int idx = base + j;
        int c = (idx < Nn) ? g_cnt[idx] : 0;
        local[j] = s;
        s += c;
    }
    part[t] = s;
    __syncthreads();
    for (int d = 1; d < 1024; d <<= 1) {
        int v = (t >= d) ? part[t - d] : 0;
        __syncthreads();
        part[t] += v;
        __syncthreads();
    }
    int excl = part[t] - s;
    #pragma unroll
    for (int j = 0; j < CH; j++) {
        int idx = base + j;
        if (idx < Nn) {
            int o = excl + local[j];
            g_off[idx] = o;
            g_cur[idx] = o;
        }
    }
    if (t == 1023) g_off[Nn] = part[1023];
}

__global__ void scatter_k(const int* __restrict__ ei) {
    int i = blockIdx.x * blockDim.x + threadIdx.x;
    if (i >= ETOT) return;
    int s, d;
    if (i < Ee) { s = ei[i]; d = ei[Ee + i]; }
    else        { s = d = i - Ee; }
    int slot = atomicAdd(&g_cur[d], 1);
    g_ssrc[slot] = s;
}

// fold attention vectors — warp per output slot; packed=1 emits V in packed k-order
__global__ void precompute_vw(const float* __restrict__ Ws, const float* __restrict__ Wd,
                              const float* __restrict__ as_, const float* __restrict__ ad_,
                              float4* __restrict__ V, int K, int C, int packed) {
    int slot = (blockIdx.x * blockDim.x + threadIdx.x) >> 5;
    int lane = threadIdx.x & 31;
    if (slot >= K) return;
    int k = packed ? pk_src(slot) : slot;
    const float* wsr = Ws + (size_t)k * 2 * C;
    const float* wdr = Wd + (size_t)k * 2 * C;
    float r0 = 0, r1 = 0, r2 = 0, r3 = 0;
    for (int c = lane; c < C; c += 32) {
        r0 += wsr[c]     * as_[c];
        r1 += wsr[C + c] * as_[C + c];
        r2 += wdr[c]     * ad_[c];
        r3 += wdr[C + c] * ad_[C + c];
    }
    #pragma unroll
    for (int d = 16; d > 0; d >>= 1) {
        r0 += __shfl_xor_sync(0xffffffffu, r0, d);
        r1 += __shfl_xor_sync(0xffffffffu, r1, d);
        r2 += __shfl_xor_sync(0xffffffffu, r2, d);
        r3 += __shfl_xor_sync(0xffffffffu, r3, d);
    }
    if (lane == 0) V[slot] = make_float4(r0, r1, r2, r3);
}

// warp-per-node GEMV: asd[n] = X[n,:] @ V (order-invariant: X and V in same order)
__global__ void gemv_asd(const float* __restrict__ X, const float4* __restrict__ V,
                         float4* __restrict__ asd, int K) {
    int w = (blockIdx.x * blockDim.x + threadIdx.x) >> 5;
    int lane = threadIdx.x & 31;
    if (w >= Nn) return;
    const float* xr = X + (size_t)w * K;
    float a0 = 0, a1 = 0, a2 = 0, a3 = 0;
    for (int k = lane; k < K; k += 32) {
        float xv = xr[k];
        float4 v = V[k];
        a0 += xv * v.x; a1 += xv * v.y; a2 += xv * v.z; a3 += xv * v.w;
    }
    #pragma unroll
    for (int d = 16; d > 0; d >>= 1) {
        a0 += __shfl_xor_sync(0xffffffffu, a0, d);
        a1 += __shfl_xor_sync(0xffffffffu, a1, d);
        a2 += __shfl_xor_sync(0xffffffffu, a2, d);
        a3 += __shfl_xor_sync(0xffffffffu, a3, d);
    }
    if (lane == 0) asd[w] = make_float4(a0, a1, a2, a3);
}

// warp-per-node segment softmax
__global__ void attn_k(const float4* __restrict__ asd) {
    int w = (blockIdx.x * blockDim.x + threadIdx.x) >> 5;
    int lane = threadIdx.x & 31;
    if (w >= Nn) return;
    float4 my = asd[w];
    float ad0 = my.z, ad1 = my.w;
    int s0 = g_off[w], s1 = g_off[w + 1];
    float m0 = -1e30f, m1 = -1e30f;
    for (int s = s0 + lane; s < s1; s += 32) {
        int src = g_ssrc[s];
        float4 sa = asd[src];
        float e0 = sa.x + ad0; e0 = (e0 > 0.f) ? e0 : 0.2f * e0;
        float e1 = sa.y + ad1; e1 = (e1 > 0.f) ? e1 : 0.2f * e1;
        g_alpha[s] = make_float2(e0, e1);
        m0 = fmaxf(m0, e0); m1 = fmaxf(m1, e1);
    }
    #pragma unroll
    for (int d = 16; d > 0; d >>= 1) {
        m0 = fmaxf(m0, __shfl_xor_sync(0xffffffffu, m0, d));
        m1 = fmaxf(m1, __shfl_xor_sync(0xffffffffu, m1, d));
    }
    float t0 = 0.f, t1 = 0.f;
    for (int s = s0 + lane; s < s1; s += 32) {
        float2 e = g_alpha[s];
        float a0 = __expf(e.x - m0);
        float a1 = __expf(e.y - m1);
        g_alpha[s] = make_float2(a0, a1);
        t0 += a0; t1 += a1;
    }
    #pragma unroll
    for (int d = 16; d > 0; d >>= 1) {
        t0 += __shfl_xor_sync(0xffffffffu, t0, d);
        t1 += __shfl_xor_sync(0xffffffffu, t1, d);
    }
    if (lane == 0) g_invd[w] = make_float2(1.f / t0, 1.f / t1);
}

// block-per-node aggregation; one thread per 8-k block; writes PACKED + tf32-rounded
template <int C>
__global__ void aggregate_k(const float* __restrict__ xs, const float* __restrict__ bias,
                            float* __restrict__ out) {
    const int F = 2 * C;
    int n = blockIdx.x;
    int tid = threadIdx.x;            // F/8 threads
    int f = tid * 8;
    int head = (f >= C) ? 1 : 0;
    int s0 = g_off[n], s1 = g_off[n + 1];
    float4 a0 = make_float4(0.f, 0.f, 0.f, 0.f);
    float4 a1 = make_float4(0.f, 0.f, 0.f, 0.f);
    for (int s = s0; s < s1; ++s) {
        int src = g_ssrc[s];
        float2 al = g_alpha[s];
        float a = head ? al.y : al.x;
        const float* vp = xs + (size_t)src * F + f;
        float4 v0 = *(const float4*)vp;
        float4 v1 = *(const float4*)(vp + 4);
        a0.x += a * v0.x; a0.y += a * v0.y; a0.z += a * v0.z; a0.w += a * v0.w;
        a1.x += a * v1.x; a1.y += a * v1.y; a1.z += a * v1.z; a1.w += a * v1.w;
    }
    float2 inv = g_invd[n];
    float ai = head ? inv.y : inv.x;
    float4 b0 = *(const float4*)(bias + f);
    float4 b1 = *(const float4*)(bias + f + 4);
    float r0 = f2tf32f(fmaxf(a0.x * ai + b0.x, 0.f));
    float r1 = f2tf32f(fmaxf(a0.y * ai + b0.y, 0.f));
    float r2 = f2tf32f(fmaxf(a0.z * ai + b0.z, 0.f));
    float r3 = f2tf32f(fmaxf(a0.w * ai + b0.w, 0.f));
    float r4 = f2tf32f(fmaxf(a1.x * ai + b1.x, 0.f));
    float r5 = f2tf32f(fmaxf(a1.y * ai + b1.y, 0.f));
    float r6 = f2tf32f(fmaxf(a1.z * ai + b1.z, 0.f));
    float r7 = f2tf32f(fmaxf(a1.w * ai + b1.w, 0.f));
    // packed: (v0,v4,v1,v5),(v2,v6,v3,v7)
    *(float4*)(out + (size_t)n * F + f)     = make_float4(r0, r4, r1, r5);
    *(float4*)(out + (size_t)n * F + f + 4) = make_float4(r2, r6, r3, r7);
}

// ---------------- TF32 legacy-mma GEMM: C[M,Nc] = A[M,K] @ B^T ----------------
// A: [M][K] packed pairs; B: [Nc][K] transposed + packed pairs (so staging for
// both operands is the SAME contiguous-8B copy). cp.async double-buffered
// pipeline: chunk c+1 streams into the alternate smem buffer while chunk c
// computes. Smem content identical to prior rounds (pair layout, GRS=10).

__device__ __forceinline__ void mma_tf32(float* d, const unsigned* a, const unsigned* b) {
    asm volatile(
        "mma.sync.aligned.m16n8k8.row.col.f32.tf32.tf32.f32 "
        "{%0,%1,%2,%3}, {%4,%5,%6,%7}, {%8,%9}, {%0,%1,%2,%3};\n"
        : "+f"(d[0]), "+f"(d[1]), "+f"(d[2]), "+f"(d[3])
        : "r"(a[0]), "r"(a[1]), "r"(a[2]), "r"(a[3]), "r"(b[0]), "r"(b[1]));
}

__device__ __forceinline__ void cp8(uint32_t dst, const float* src, int valid) {
    asm volatile("cp.async.ca.shared.global [%0], [%1], 8, %2;"
                 :: "r"(dst), "l"(src), "r"(valid ? 8 : 0));
}

#define GRS 10                        // smem row stride in words
#define SREG (128 * GRS + 8)          // 1288 words per k-block region
#define BUFW (4 * SREG)               // words per operand buffer (one chunk)
#define GSMEM (4 * BUFW * 4)          // total dynamic smem bytes (2 bufs x A+B)

__global__ void __launch_bounds__(256, 2)
mma_gemm_k(const float* __restrict__ A, const float* __restrict__ B,
           float* __restrict__ Cm, int M, int Nc, int Ktot, int Ksplit) {
    extern __shared__ __align__(16) unsigned sm[];
    uint32_t sb;
    asm("{ .reg .u64 t; cvta.to.shared.u64 t, %1; cvt.u32.u64 %0, t; }" : "=r"(sb) : "l"(sm));

    int tid = threadIdx.x;
    int lane = tid & 31;
    int w = tid >> 5;
    int warp_m = w >> 2;         // 0..1 -> 64-row group
    int warp_n = w & 3;          // 0..3 -> 32-col group
    int m0 = blockIdx.y * 128;
    int n0 = blockIdx.x * 128;
    int kbeg = blockIdx.z * Ksplit;
    Cm += (size_t)blockIdx.z * M * Nc;
    int lr = lane >> 2;          // 0..7
    int lc = lane & 3;           // 0..3

    float acc[4][4][4];
    #pragma unroll
    for (int mt = 0; mt < 4; mt++)
        #pragma unroll
        for (int nt = 0; nt < 4; nt++)
            #pragma unroll
            for (int e = 0; e < 4; e++) acc[mt][nt][e] = 0.f;

    int nch = Ksplit / 32;

    // staging: 8 tasks/thread each for A and B; task = one 8B pair-chunk
    // task t: row = t>>4 (0..127), kb = (t>>2)&3, q = t&3
    #define STAGE(buf, k0) do {                                                \
        uint32_t abase = sb + (buf) * 2 * BUFW * 4;                            \
        uint32_t bbase = abase + BUFW * 4;                                     \
        _Pragma("unroll")                                                      \
        for (int j = 0; j < 8; j++) {                                          \
            int t = j * 256 + tid;                                             \
            int row = t >> 4, kb = (t >> 2) & 3, q = t & 3;                    \
            int off = (kb * SREG + row * GRS + 2 * q) * 4;                     \
            int gr = m0 + row;                                                 \
            const float* as = A + (size_t)(gr < M ? gr : 0) * Ktot + (k0) + kb * 8 + 2 * q; \
            cp8(abase + off, as, gr < M);                                      \
            const float* bs = B + (size_t)(n0 + row) * Ktot + (k0) + kb * 8 + 2 * q; \
            cp8(bbase + off, bs, 1);                                           \
        }                                                                      \
        asm volatile("cp.async.commit_group;");                                \
    } while (0)

    STAGE(0, kbeg);

    for (int c = 0; c < nch; c++) {
        if (c + 1 < nch) {
            STAGE((c + 1) & 1, kbeg + (c + 1) * 32);
            asm volatile("cp.async.wait_group 1;");
        } else {
            asm volatile("cp.async.wait_group 0;");
        }
        __syncthreads();

        unsigned* As = sm + (c & 1) * 2 * BUFW;
        unsigned* Bs = As + BUFW;

        #pragma unroll
        for (int ks = 0; ks < 4; ks++) {
            unsigned a[4][4];
            #pragma unroll
            for (int mt = 0; mt < 4; mt++) {
                int r = warp_m * 64 + mt * 16 + lr;
                uint2 x0 = *(const uint2*)&As[ks * SREG + r * GRS + 2 * lc];
                uint2 x1 = *(const uint2*)&As[ks * SREG + (r + 8) * GRS + 2 * lc];
                a[mt][0] = x0.x; a[mt][2] = x0.y;      // k = lc, lc+4 (row r)
                a[mt][1] = x1.x; a[mt][3] = x1.y;      // row r+8
            }
            #pragma unroll
            for (int nt = 0; nt < 4; nt++) {
                int n = warp_n * 32 + nt * 8 + lr;
                uint2 y = *(const uint2*)&Bs[ks * SREG + n * GRS + 2 * lc];
                unsigned b[2] = { y.x, y.y };
                #pragma unroll
                for (int mt = 0; mt < 4; mt++)
                    mma_tf32(acc[mt][nt], a[mt], b);
            }
        }
        __syncthreads();   // everyone done reading buf c&1 before restaging it
    }

    // epilogue (no bias — biases handled downstream)
    #pragma unroll
    for (int mt = 0; mt < 4; mt++) {
        int r0 = m0 + warp_m * 64 + mt * 16 + lr;
        int r1 = r0 + 8;
        #pragma unroll
        for (int nt = 0; nt < 4; nt++) {
            int c = n0 + warp_n * 32 + nt * 8 + 2 * lc;
            if (r0 < M) {
                float2 v = make_float2(acc[mt][nt][0], acc[mt][nt][1]);
                *(float2*)(Cm + (size_t)r0 * Nc + c) = v;
            }
            if (r1 < M) {
                float2 v = make_float2(acc[mt][nt][2], acc[mt][nt][3]);
                *(float2*)(Cm + (size_t)r1 * Nc + c) = v;
            }
        }
    }
}

// combine gemm3 split-K partials + bias
__global__ void reduce3_k(const float* __restrict__ part, const float* __restrict__ bias,
                          float* __restrict__ z) {
    int i = blockIdx.x * blockDim.x + threadIdx.x;
    if (i >= Nn * HID) return;
    const int MN = Nn * HID;
    float s = part[i] + part[i + MN] + part[i + 2 * MN] + part[i + 3 * MN] + bias[i & (HID - 1)];
    z[i] = s;
}

// ---------------- MLP head ----------------
__global__ void stats_k() {
    int t = threadIdx.x;                       // 128 = HID
    int per = (Nn + gridDim.x - 1) / gridDim.x;
    int n0 = blockIdx.x * per;
    int n1 = min(Nn, n0 + per);
    float s = 0.f, ss = 0.f;
    for (int n = n0; n < n1; n++) {
        float v = g_z[(size_t)n * HID + t];
        s += v; ss += v * v;
    }
    atomicAdd(&g_sum[t], s);
    atomicAdd(&g_ss[t], ss);
}

__global__ void finalize_k() {
    int t = threadIdx.x;
    float m = g_sum[t] / (float)Nn;
    float v = g_ss[t] / (float)Nn - m * m;
    g_mean[t] = m;
    g_rstd[t] = rsqrtf(v + 1e-5f);
}

// warp-per-node: layernorm -> relu -> @wf2+bf2 -> log_softmax
__global__ void head_k(const float* __restrict__ gamma, const float* __restrict__ beta,
                       const float* __restrict__ wf2, const float* __restrict__ bf2,
                       float* __restrict__ out) {
    int w = (blockIdx.x * blockDim.x + threadIdx.x) >> 5;
    int lane = threadIdx.x & 31;
    if (w >= Nn) return;
    float4 zv = *(const float4*)(g_z + (size_t)w * HID + lane * 4);
    float4 gm = *(const float4*)(gamma + lane * 4);
    float4 bt = *(const float4*)(beta + lane * 4);
    float4 mn = *(const float4*)(g_mean + lane * 4);
    float4 rs = *(const float4*)(g_rstd + lane * 4);
    float vv[4];
    vv[0] = fmaxf(gm.x * (zv.x - mn.x) * rs.x + bt.x, 0.f);
    vv[1] = fmaxf(gm.y * (zv.y - mn.y) * rs.y + bt.y, 0.f);
    vv[2] = fmaxf(gm.z * (zv.z - mn.z) * rs.z + bt.z, 0.f);
    vv[3] = fmaxf(gm.w * (zv.w - mn.w) * rs.w + bt.w, 0.f);
    float p0 = 0.f, p1 = 0.f, p2 = 0.f;
    #pragma unroll
    for (int j = 0; j < 4; j++) {
        int f = lane * 4 + j;
        p0 += vv[j] * wf2[f * 3 + 0];
        p1 += vv[j] * wf2[f * 3 + 1];
        p2 += vv[j] * wf2[f * 3 + 2];
    }
    #pragma unroll
    for (int d = 16; d > 0; d >>= 1) {
        p0 += __shfl_xor_sync(0xffffffffu, p0, d);
        p1 += __shfl_xor_sync(0xffffffffu, p1, d);
        p2 += __shfl_xor_sync(0xffffffffu, p2, d);
    }
    if (lane == 0) {
        float l0 = p0 + bf2[0], l1 = p1 + bf2[1], l2 = p2 + bf2[2];
        float mx = fmaxf(l0, fmaxf(l1, l2));
        float se = expf(l0 - mx) + expf(l1 - mx) + expf(l2 - mx);
        float ls = mx + logf(se);
        out[w * 3 + 0] = l0 - ls;
        out[w * 3 + 1] = l1 - ls;
        out[w * 3 + 2] = l2 - ls;
    }
}

// ---------------- launch ----------------
#define GETSYM(T, var, sym) T var; { void* _p = nullptr; cudaGetSymbolAddress(&_p, sym); var = (T)_p; }

extern "C" void kernel_launch(void* const* d_in, const int* in_sizes, int n_in,
                              void* d_out, int out_size) {
    const float* x   = (const float*)d_in[0];
    const int*   ei  = (const int*)  d_in[1];
    const float* w1s = (const float*)d_in[2];
    const float* w1d = (const float*)d_in[3];
    const float* a1s = (const float*)d_in[4];
    const float* a1d = (const float*)d_in[5];
    const float* b1  = (const float*)d_in[6];
    const float* w2s = (const float*)d_in[7];
    const float* w2d = (const float*)d_in[8];
    const float* a2s = (const float*)d_in[9];
    const float* a2d = (const float*)d_in[10];
    const float* b2  = (const float*)d_in[11];
    const float* wf1 = (const float*)d_in[12];
    const float* bf1 = (const float*)d_in[13];
    const float* gamma = (const float*)d_in[14];
    const float* beta  = (const float*)d_in[15];
    const float* wf2 = (const float*)d_in[16];
    const float* bf2 = (const float*)d_in[17];
    float* out = (float*)d_out;

    GETSYM(float*,  xs1, g_xs1);  GETSYM(float*,  h1,  g_h1);
    GETSYM(float*,  xs2, g_xs2);  GETSYM(float*,  h2,  g_h2);
    GETSYM(float*,  z,   g_z);
    GETSYM(float*,  xtf, g_xtf);  GETSYM(float*,  w1tf, g_w1tf);
    GETSYM(float*,  w2tf, g_w2tf); GETSYM(float*, wftf, g_wftf);
    GETSYM(float4*, asd1, g_asd1); GETSYM(float4*, asd2, g_asd2);
    GETSYM(float4*, v1, g_v1);     GETSYM(float4*, v2, g_v2);

    static int smem_set = 0;
    if (!smem_set) {
        cudaFuncSetAttribute(mma_gemm_k, cudaFuncAttributeMaxDynamicSharedMemorySize, GSMEM);
        smem_set = 1;
    }

    const int TPB = 256;
    int egrid = (ETOT + TPB - 1) / TPB;
    int wgrid = (Nn * 32 + TPB - 1) / TPB;      // warp-per-node grids
    int mgrid = (Nn + 127) / 128;               // 79 row tiles
    int rgrid = (NX + NW1 + NW2 + NWF + TPB - 1) / TPB;

    // launch order arranged so gemm1 sits at index 3 (the ncu-profiled slot)
    round_all<<<rgrid, TPB>>>(x, w1s, w2s, wf1);                     // 0
    zero_k<<<(Nn + TPB - 1) / TPB, TPB>>>();                         // 1
    count_k<<<egrid, TPB>>>(ei);                                     // 2
    {
        dim3 g(F1 / 128, mgrid, 1);                                  // 3  <- profiled
        mma_gemm_k<<<g, 256, GSMEM>>>(xtf, w1tf, xs1, Nn, F1, DIN, DIN);
    }
    scan_k<<<1, 1024>>>();                                           // 4
    scatter_k<<<egrid, TPB>>>(ei);                                   // 5

    // ---- layer 1 (attention path uses exact fp32 x / weights) ----
    precompute_vw<<<(DIN * 32 + TPB - 1) / TPB, TPB>>>(w1s, w1d, a1s, a1d, v1, DIN, C1, 0);
    gemv_asd<<<wgrid, TPB>>>(x, v1, asd1, DIN);
    attn_k<<<wgrid, TPB>>>(asd1);
    aggregate_k<C1><<<Nn, F1 / 8>>>(xs1, b1, h1);   // h1 packed+rounded

    // ---- layer 2 (h1 packed; v2 emitted in packed order) ----
    precompute_vw<<<(F1 * 32 + TPB - 1) / TPB, TPB>>>(w2s, w2d, a2s, a2d, v2, F1, C2, 1);
    {
        dim3 g(F2 / 128, mgrid, 1);
        mma_gemm_k<<<g, 256, GSMEM>>>(h1, w2tf, xs2, Nn, F2, F1, F1);
    }
    gemv_asd<<<wgrid, TPB>>>(h1, v2, asd2, F1);
    attn_k<<<wgrid, TPB>>>(asd2);
    aggregate_k<C2><<<Nn, F2 / 8>>>(xs2, b2, h2);   // h2 packed+rounded

    // ---- MLP head: gemm3 split-K=4 into partials (reuse g_xs2), then reduce ----
    {
        dim3 g(HID / 128, mgrid, 4);                // 1 x 79 x 4 = 316 CTAs
        mma_gemm_k<<<g, 256, GSMEM>>>(h2, wftf, xs2, Nn, HID, F2, F2 / 4);
    }
    reduce3_k<<<(Nn * HID + TPB - 1) / TPB, TPB>>>(xs2, bf1, z);
    stats_k<<<128, HID>>>();
    finalize_k<<<1, HID>>>();
    head_k<<<wgrid, TPB>>>(gamma, beta, wf2, bf2, out);
}

// round 17
// speedup vs baseline: 1.1971x; 1.1971x over previous
#include <cuda_runtime.h>
#include <cuda_bf16.h>
#include <stdint.h>
#include <math.h>

// ---------------- problem constants ----------------
#define Nn    10000
#define Ee    160000
#define ETOT  170000          // edges + self loops
#define DIN   256
#define F1    512             // H*C1
#define C1    256
#define F2    1024            // H*C2
#define C2    512
#define HID   128
#define NOUT  3

#define NX   (Nn * DIN)       // 2,560,000
#define NW1  (DIN * F1)       // 131,072
#define NW2  (F1 * F2)        // 524,288
#define NWF  (F2 * HID)       // 131,072

// ---------------- device scratch (static, no allocs) ----------------
__device__ float  g_xs1[(size_t)Nn * F1];
__device__ float  g_h1 [(size_t)Nn * F1];
__device__ float  g_xs2[(size_t)Nn * F2];   // also reused as gemm3 split-K partials
__device__ float  g_h2 [(size_t)Nn * F2];
__device__ float  g_z  [(size_t)Nn * HID];
__device__ float  g_xtf[NX];             // tf32-rounded x
__device__ float  g_w1tf[NW1];           // tf32-rounded w1s
__device__ float  g_w2tf[NW2];           // tf32-rounded w2s
__device__ float  g_wftf[NWF];           // tf32-rounded wf1
__device__ float4 g_asd1[Nn];            // (a_s h0, a_s h1, a_d h0, a_d h1)
__device__ float4 g_asd2[Nn];
__device__ float2 g_alpha[ETOT];         // per-slot e then unnormalized alpha
__device__ float2 g_invd[Nn];            // 1/denom per head
__device__ int    g_cnt[Nn];
__device__ int    g_off[Nn + 1];
__device__ int    g_cur[Nn];
__device__ int    g_ssrc[ETOT];          // CSR (grouped by dst): src node per slot
__device__ float4 g_v1[DIN];             // folded attention vectors layer1
__device__ float4 g_v2[F1];              // folded attention vectors layer2
__device__ float  g_sum[HID], g_ss[HID], g_mean[HID], g_rstd[HID];

__device__ __forceinline__ unsigned f2tf32(float f) {
    unsigned u;
    asm("cvt.rna.tf32.f32 %0, %1;" : "=r"(u) : "f"(f));
    return u;
}
__device__ __forceinline__ float f2tf32f(float f) {
    return __uint_as_float(f2tf32(f));
}

// one-shot pre-rounding of all static mma operands (x + 3 weight matrices)
__global__ void round_all(const float* __restrict__ x, const float* __restrict__ w1s,
                          const float* __restrict__ w2s, const float* __restrict__ wf1) {
    int i = blockIdx.x * blockDim.x + threadIdx.x;
    if (i < NX) { g_xtf[i] = f2tf32f(x[i]); return; }
    i -= NX;
    if (i < NW1) { g_w1tf[i] = f2tf32f(w1s[i]); return; }
    i -= NW1;
    if (i < NW2) { g_w2tf[i] = f2tf32f(w2s[i]); return; }
    i -= NW2;
    if (i < NWF) { g_wftf[i] = f2tf32f(wf1[i]); return; }
}

// ---------------- small utility kernels ----------------
__global__ void zero_k() {
    int i = blockIdx.x * blockDim.x + threadIdx.x;
    if (i < Nn) g_cnt[i] = 0;
    if (i < HID) { g_sum[i] = 0.f; g_ss[i] = 0.f; }
}

__global__ void count_k(const int* __restrict__ ei) {
    int i = blockIdx.x * blockDim.x + threadIdx.x;
    if (i >= ETOT) return;
    int d = (i < Ee) ? ei[Ee + i] : (i - Ee);
    atomicAdd(&g_cnt[d], 1);
}

// single block exclusive scan over g_cnt -> g_off (+ g_cur copy), 1024 threads
__global__ void scan_k() {
    __shared__ int part[1024];
    const int CH = 10;                       // 1024*10 >= Nn
    int t = threadIdx.x;
    int base = t * CH;
    int local[CH];
    int s = 0;
    #pragma unroll
    for (int j = 0; j < CH; j++) {
        int idx = base + j;
        int c = (idx < Nn) ? g_cnt[idx] : 0;
        local[j] = s;
        s += c;
    }
    part[t] = s;
    __syncthreads();
    for (int d = 1; d < 1024; d <<= 1) {
        int v = (t >= d) ? part[t - d] : 0;
        __syncthreads();
        part[t] += v;
        __syncthreads();
    }
    int excl = part[t] - s;
    #pragma unroll
    for (int j = 0; j < CH; j++) {
        int idx = base + j;
        if (idx < Nn) {
            int o = excl + local[j];
            g_off[idx] = o;
            g_cur[idx] = o;
        }
    }
    if (t == 1023) g_off[Nn] = part[1023];
}

__global__ void scatter_k(const int* __restrict__ ei) {
    int i = blockIdx.x * blockDim.x + threadIdx.x;
    if (i >= ETOT) return;
    int s, d;
    if (i < Ee) { s = ei[i]; d = ei[Ee + i]; }
    else        { s = d = i - Ee; }
    int slot = atomicAdd(&g_cur[d], 1);
    g_ssrc[slot] = s;
}

// fold attention vectors into the weight matrices — warp per output row
__global__ void precompute_vw(const float* __restrict__ Ws, const float* __restrict__ Wd,
                              const float* __restrict__ as_, const float* __restrict__ ad_,
                              float4* __restrict__ V, int K, int C) {
    int w = (blockIdx.x * blockDim.x + threadIdx.x) >> 5;
    int lane = threadIdx.x & 31;
    if (w >= K) return;
    const float* wsr = Ws + (size_t)w * 2 * C;
    const float* wdr = Wd + (size_t)w * 2 * C;
    float r0 = 0, r1 = 0, r2 = 0, r3 = 0;
    for (int c = lane; c < C; c += 32) {
        r0 += wsr[c]     * as_[c];
        r1 += wsr[C + c] * as_[C + c];
        r2 += wdr[c]     * ad_[c];
        r3 += wdr[C + c] * ad_[C + c];
    }
    #pragma unroll
    for (int d = 16; d > 0; d >>= 1) {
        r0 += __shfl_xor_sync(0xffffffffu, r0, d);
        r1 += __shfl_xor_sync(0xffffffffu, r1, d);
        r2 += __shfl_xor_sync(0xffffffffu, r2, d);
        r3 += __shfl_xor_sync(0xffffffffu, r3, d);
    }
    if (lane == 0) V[w] = make_float4(r0, r1, r2, r3);
}

// warp-per-node GEMV: asd[n] = X[n,:] @ V  (4 outputs)
__global__ void gemv_asd(const float* __restrict__ X, const float4* __restrict__ V,
                         float4* __restrict__ asd, int K) {
    int w = (blockIdx.x * blockDim.x + threadIdx.x) >> 5;
    int lane = threadIdx.x & 31;
    if (w >= Nn) return;
    const float* xr = X + (size_t)w * K;
    float a0 = 0, a1 = 0, a2 = 0, a3 = 0;
    for (int k = lane; k < K; k += 32) {
        float xv = xr[k];
        float4 v = V[k];
        a0 += xv * v.x; a1 += xv * v.y; a2 += xv * v.z; a3 += xv * v.w;
    }
    #pragma unroll
    for (int d = 16; d > 0; d >>= 1) {
        a0 += __shfl_xor_sync(0xffffffffu, a0, d);
        a1 += __shfl_xor_sync(0xffffffffu, a1, d);
        a2 += __shfl_xor_sync(0xffffffffu, a2, d);
        a3 += __shfl_xor_sync(0xffffffffu, a3, d);
    }
    if (lane == 0) asd[w] = make_float4(a0, a1, a2, a3);
}

// warp-per-node segment softmax
__global__ void attn_k(const float4* __restrict__ asd) {
    int w = (blockIdx.x * blockDim.x + threadIdx.x) >> 5;
    int lane = threadIdx.x & 31;
    if (w >= Nn) return;
    float4 my = asd[w];
    float ad0 = my.z, ad1 = my.w;
    int s0 = g_off[w], s1 = g_off[w + 1];
    float m0 = -1e30f, m1 = -1e30f;
    for (int s = s0 + lane; s < s1; s += 32) {
        int src = g_ssrc[s];
        float4 sa = asd[src];
        float e0 = sa.x + ad0; e0 = (e0 > 0.f) ? e0 : 0.2f * e0;
        float e1 = sa.y + ad1; e1 = (e1 > 0.f) ? e1 : 0.2f * e1;
        g_alpha[s] = make_float2(e0, e1);
        m0 = fmaxf(m0, e0); m1 = fmaxf(m1, e1);
    }
    #pragma unroll
    for (int d = 16; d > 0; d >>= 1) {
        m0 = fmaxf(m0, __shfl_xor_sync(0xffffffffu, m0, d));
        m1 = fmaxf(m1, __shfl_xor_sync(0xffffffffu, m1, d));
    }
    float t0 = 0.f, t1 = 0.f;
    for (int s = s0 + lane; s < s1; s += 32) {
        float2 e = g_alpha[s];
        float a0 = __expf(e.x - m0);
        float a1 = __expf(e.y - m1);
        g_alpha[s] = make_float2(a0, a1);
        t0 += a0; t1 += a1;
    }
    #pragma unroll
    for (int d = 16; d > 0; d >>= 1) {
        t0 += __shfl_xor_sync(0xffffffffu, t0, d);
        t1 += __shfl_xor_sync(0xffffffffu, t1, d);
    }
    if (lane == 0) g_invd[w] = make_float2(1.f / t0, 1.f / t1);
}

// block-per-node aggregation; output pre-rounded to tf32 grid (feeds next GEMM A)
template <int C>
__global__ void aggregate_k(const float* __restrict__ xs, const float* __restrict__ bias,
                            float* __restrict__ out) {
    const int F = 2 * C;
    int n = blockIdx.x;
    int tid = threadIdx.x;            // F/4 threads
    int f = tid * 4;
    int head = (f >= C) ? 1 : 0;
    int s0 = g_off[n], s1 = g_off[n + 1];
    float4 acc = make_float4(0.f, 0.f, 0.f, 0.f);
    for (int s = s0; s < s1; ++s) {
        int src = g_ssrc[s];
        float2 al = g_alpha[s];
        float a = head ? al.y : al.x;
        float4 v = *(const float4*)(xs + (size_t)src * F + f);
        acc.x += a * v.x; acc.y += a * v.y; acc.z += a * v.z; acc.w += a * v.w;
    }
    float2 inv = g_invd[n];
    float ai = head ? inv.y : inv.x;
    float4 b4 = *(const float4*)(bias + f);
    float4 r;
    r.x = f2tf32f(fmaxf(acc.x * ai + b4.x, 0.f));
    r.y = f2tf32f(fmaxf(acc.y * ai + b4.y, 0.f));
    r.z = f2tf32f(fmaxf(acc.z * ai + b4.z, 0.f));
    r.w = f2tf32f(fmaxf(acc.w * ai + b4.w, 0.f));
    *(float4*)(out + (size_t)n * F + f) = r;
}

// ---------------- TF32 legacy-mma GEMM: C[M,Nc] = A[M,K] @ B[K,Nc] ----------------
// Operands PRE-ROUNDED to tf32 grid in gmem — staging is a pure copy.
// CTA tile 128x128, K-chunk 32, 8 warps (2m x 4n), warp tile 64x32, mma.m16n8k8.tf32.
// SMEM: per-8k-block regions of stride 128*GRS+8 words; the +8 de-aligns region
// bases mod 32 banks, making staging pair-writes (STS.64 of (k, k+4)) a perfect
// bank bijection. Fragment reads are uint2 at row*GRS + 2*lc — conflict-free.
// Split-K via blockIdx.z (partials, no bias).

__device__ __forceinline__ void mma_tf32(float* d, const unsigned* a, const unsigned* b) {
    asm volatile(
        "mma.sync.aligned.m16n8k8.row.col.f32.tf32.tf32.f32 "
        "{%0,%1,%2,%3}, {%4,%5,%6,%7}, {%8,%9}, {%0,%1,%2,%3};\n"
        : "+f"(d[0]), "+f"(d[1]), "+f"(d[2]), "+f"(d[3])
        : "r"(a[0]), "r"(a[1]), "r"(a[2]), "r"(a[3]), "r"(b[0]), "r"(b[1]));
}

#define GRS 10                        // smem row stride in words
#define SREG (128 * GRS + 8)          // 1288 words per k-block region (A and B)

__global__ void __launch_bounds__(256, 2)
mma_gemm_k(const float* __restrict__ A, const float* __restrict__ B,
           float* __restrict__ Cm, int M, int Nc, int Ktot, int Ksplit) {
    __shared__ __align__(16) unsigned As[4 * SREG];   // ~20.1 KB
    __shared__ __align__(16) unsigned Bs[4 * SREG];   // ~20.1 KB

    int tid = threadIdx.x;
    int lane = tid & 31;
    int w = tid >> 5;
    int warp_m = w >> 2;         // 0..1 -> 64-row group
    int warp_n = w & 3;          // 0..3 -> 32-col group
    int m0 = blockIdx.y * 128;
    int n0 = blockIdx.x * 128;
    int kbeg = blockIdx.z * Ksplit;
    Cm += (size_t)blockIdx.z * M * Nc;
    int lr = lane >> 2;          // 0..7
    int lc = lane & 3;           // 0..3

    float acc[4][4][4];
    #pragma unroll
    for (int mt = 0; mt < 4; mt++)
        #pragma unroll
        for (int nt = 0; nt < 4; nt++)
            #pragma unroll
            for (int e = 0; e < 4; e++) acc[mt][nt][e] = 0.f;

    for (int k0 = kbeg; k0 < kbeg + Ksplit; k0 += 32) {
        __syncthreads();
        // stage A: 2 tasks/thread; task = full 8-k block of one row
        #pragma unroll
        for (int j = 0; j < 2; j++) {
            int t = j * 256 + tid;
            int row = t >> 2, kb = t & 3;
            int gr = m0 + row;
            uint4 v0, v1;
            if (gr < M) {
                const float* ap = A + (size_t)gr * Ktot + k0 + kb * 8;
                v0 = *(const uint4*)ap;
                v1 = *(const uint4*)(ap + 4);
            } else {
                v0 = make_uint4(0u, 0u, 0u, 0u); v1 = v0;
            }
            unsigned* dst = &As[kb * SREG + row * GRS];
            *(uint2*)&dst[0] = make_uint2(v0.x, v1.x);
            *(uint2*)&dst[2] = make_uint2(v0.y, v1.y);
            *(uint2*)&dst[4] = make_uint2(v0.z, v1.z);
            *(uint2*)&dst[6] = make_uint2(v0.w, v1.w);
        }
        // stage B: 2 tasks/thread; task = pair (k, k+4) for a 4-col quad
        #pragma unroll
        for (int j = 0; j < 2; j++) {
            int t = j * 256 + tid;
            int kk = (t >> 2) & 3;
            int kb = (t >> 4) & 3;
            int nq = ((t >> 6) << 2) | (t & 3);
            const float* bp = B + (size_t)(k0 + kb * 8 + kk) * Nc + n0 + nq * 4;
            uint4 v0 = *(const uint4*)bp;
            uint4 v1 = *(const uint4*)(bp + (size_t)4 * Nc);
            unsigned* dst = &Bs[kb * SREG + (nq * 4) * GRS + kk * 2];
            *(uint2*)&dst[0 * GRS] = make_uint2(v0.x, v1.x);
            *(uint2*)&dst[1 * GRS] = make_uint2(v0.y, v1.y);
            *(uint2*)&dst[2 * GRS] = make_uint2(v0.z, v1.z);
            *(uint2*)&dst[3 * GRS] = make_uint2(v0.w, v1.w);
        }
        __syncthreads();

        #pragma unroll
        for (int ks = 0; ks < 4; ks++) {
            unsigned a[4][4];
            #pragma unroll
            for (int mt = 0; mt < 4; mt++) {
                int r = warp_m * 64 + mt * 16 + lr;
                uint2 x0 = *(const uint2*)&As[ks * SREG + r * GRS + 2 * lc];
                uint2 x1 = *(const uint2*)&As[ks * SREG + (r + 8) * GRS + 2 * lc];
                a[mt][0] = x0.x; a[mt][2] = x0.y;      // k = lc, lc+4 (row r)
                a[mt][1] = x1.x; a[mt][3] = x1.y;      // row r+8
            }
            #pragma unroll
            for (int nt = 0; nt < 4; nt++) {
                int n = warp_n * 32 + nt * 8 + lr;
                uint2 y = *(const uint2*)&Bs[ks * SREG + n * GRS + 2 * lc];
                unsigned b[2] = { y.x, y.y };
                #pragma unroll
                for (int mt = 0; mt < 4; mt++)
                    mma_tf32(acc[mt][nt], a[mt], b);
            }
        }
    }

    // epilogue (no bias — biases handled downstream)
    #pragma unroll
    for (int mt = 0; mt < 4; mt++) {
        int r0 = m0 + warp_m * 64 + mt * 16 + lr;
        int r1 = r0 + 8;
        #pragma unroll
        for (int nt = 0; nt < 4; nt++) {
            int c = n0 + warp_n * 32 + nt * 8 + 2 * lc;
            if (r0 < M) {
                float2 v = make_float2(acc[mt][nt][0], acc[mt][nt][1]);
                *(float2*)(Cm + (size_t)r0 * Nc + c) = v;
            }
            if (r1 < M) {
                float2 v = make_float2(acc[mt][nt][2], acc[mt][nt][3]);
                *(float2*)(Cm + (size_t)r1 * Nc + c) = v;
            }
        }
    }
}

// combine gemm3 split-K partials + bias
__global__ void reduce3_k(const float* __restrict__ part, const float* __restrict__ bias,
                          float* __restrict__ z) {
    int i = blockIdx.x * blockDim.x + threadIdx.x;
    if (i >= Nn * HID) return;
    const int MN = Nn * HID;
    float s = part[i] + part[i + MN] + part[i + 2 * MN] + part[i + 3 * MN] + bias[i & (HID - 1)];
    z[i] = s;
}

// ---------------- MLP head ----------------
__global__ void stats_k() {
    int t = threadIdx.x;                       // 128 = HID
    int per = (Nn + gridDim.x - 1) / gridDim.x;
    int n0 = blockIdx.x * per;
    int n1 = min(Nn, n0 + per);
    float s = 0.f, ss = 0.f;
    for (int n = n0; n < n1; n++) {
        float v = g_z[(size_t)n * HID + t];
        s += v; ss += v * v;
    }
    atomicAdd(&g_sum[t], s);
    atomicAdd(&g_ss[t], ss);
}

__global__ void finalize_k() {
    int t = threadIdx.x;
    float m = g_sum[t] / (float)Nn;
    float v = g_ss[t] / (float)Nn - m * m;
    g_mean[t] = m;
    g_rstd[t] = rsqrtf(v + 1e-5f);
}

// warp-per-node: layernorm -> relu -> @wf2+bf2 -> log_softmax
__global__ void head_k(const float* __restrict__ gamma, const float* __restrict__ beta,
                       const float* __restrict__ wf2, const float* __restrict__ bf2,
                       float* __restrict__ out) {
    int w = (blockIdx.x * blockDim.x + threadIdx.x) >> 5;
    int lane = threadIdx.x & 31;
    if (w >= Nn) return;
    float4 zv = *(const float4*)(g_z + (size_t)w * HID + lane * 4);
    float4 gm = *(const float4*)(gamma + lane * 4);
    float4 bt = *(const float4*)(beta + lane * 4);
    float4 mn = *(const float4*)(g_mean + lane * 4);
    float4 rs = *(const float4*)(g_rstd + lane * 4);
    float vv[4];
    vv[0] = fmaxf(gm.x * (zv.x - mn.x) * rs.x + bt.x, 0.f);
    vv[1] = fmaxf(gm.y * (zv.y - mn.y) * rs.y + bt.y, 0.f);
    vv[2] = fmaxf(gm.z * (zv.z - mn.z) * rs.z + bt.z, 0.f);
    vv[3] = fmaxf(gm.w * (zv.w - mn.w) * rs.w + bt.w, 0.f);
    float p0 = 0.f, p1 = 0.f, p2 = 0.f;
    #pragma unroll
    for (int j = 0; j < 4; j++) {
        int f = lane * 4 + j;
        p0 += vv[j] * wf2[f * 3 + 0];
        p1 += vv[j] * wf2[f * 3 + 1];
        p2 += vv[j] * wf2[f * 3 + 2];
    }
    #pragma unroll
    for (int d = 16; d > 0; d >>= 1) {
        p0 += __shfl_xor_sync(0xffffffffu, p0, d);
        p1 += __shfl_xor_sync(0xffffffffu, p1, d);
        p2 += __shfl_xor_sync(0xffffffffu, p2, d);
    }
    if (lane == 0) {
        float l0 = p0 + bf2[0], l1 = p1 + bf2[1], l2 = p2 + bf2[2];
        float mx = fmaxf(l0, fmaxf(l1, l2));
        float se = expf(l0 - mx) + expf(l1 - mx) + expf(l2 - mx);
        float ls = mx + logf(se);
        out[w * 3 + 0] = l0 - ls;
        out[w * 3 + 1] = l1 - ls;
        out[w * 3 + 2] = l2 - ls;
    }
}

// ---------------- launch (fork-join stream graph) ----------------
#define GETSYM(T, var, sym) T var; { void* _p = nullptr; cudaGetSymbolAddress(&_p, sym); var = (T)_p; }

extern "C" void kernel_launch(void* const* d_in, const int* in_sizes, int n_in,
                              void* d_out, int out_size) {
    const float* x   = (const float*)d_in[0];
    const int*   ei  = (const int*)  d_in[1];
    const float* w1s = (const float*)d_in[2];
    const float* w1d = (const float*)d_in[3];
    const float* a1s = (const float*)d_in[4];
    const float* a1d = (const float*)d_in[5];
    const float* b1  = (const float*)d_in[6];
    const float* w2s = (const float*)d_in[7];
    const float* w2d = (const float*)d_in[8];
    const float* a2s = (const float*)d_in[9];
    const float* a2d = (const float*)d_in[10];
    const float* b2  = (const float*)d_in[11];
    const float* wf1 = (const float*)d_in[12];
    const float* bf1 = (const float*)d_in[13];
    const float* gamma = (const float*)d_in[14];
    const float* beta  = (const float*)d_in[15];
    const float* wf2 = (const float*)d_in[16];
    const float* bf2 = (const float*)d_in[17];
    float* out = (float*)d_out;

    GETSYM(float*,  xs1, g_xs1);  GETSYM(float*,  h1,  g_h1);
    GETSYM(float*,  xs2, g_xs2);  GETSYM(float*,  h2,  g_h2);
    GETSYM(float*,  z,   g_z);
    GETSYM(float*,  xtf, g_xtf);  GETSYM(float*,  w1tf, g_w1tf);
    GETSYM(float*,  w2tf, g_w2tf); GETSYM(float*, wftf, g_wftf);
    GETSYM(float4*, asd1, g_asd1); GETSYM(float4*, asd2, g_asd2);
    GETSYM(float4*, v1, g_v1);     GETSYM(float4*, v2, g_v2);

    // side streams / events, created once (same structure every call)
    static cudaStream_t s1 = nullptr, s2 = nullptr;
    static cudaEvent_t eA = nullptr, e1 = nullptr, e2 = nullptr, eB = nullptr, e3 = nullptr;
    if (!s1) {
        cudaStreamCreateWithFlags(&s1, cudaStreamNonBlocking);
        cudaStreamCreateWithFlags(&s2, cudaStreamNonBlocking);
        cudaEventCreateWithFlags(&eA, cudaEventDisableTiming);
        cudaEventCreateWithFlags(&e1, cudaEventDisableTiming);
        cudaEventCreateWithFlags(&e2, cudaEventDisableTiming);
        cudaEventCreateWithFlags(&eB, cudaEventDisableTiming);
        cudaEventCreateWithFlags(&e3, cudaEventDisableTiming);
    }
    cudaStream_t m = 0;   // legacy default stream (captured by harness)

    const int TPB = 256;
    int egrid = (ETOT + TPB - 1) / TPB;
    int wgrid = (Nn * 32 + TPB - 1) / TPB;      // warp-per-node grids
    int mgrid = (Nn + 127) / 128;               // 79 row tiles
    int rgrid = (NX + NW1 + NW2 + NWF + TPB - 1) / TPB;

    // ---- fork A: CSR+attn1 chain (s1) and precompute_v2 (s2) run alongside
    //      round_all+gemm1 on the main stream ----
    cudaEventRecord(eA, m);
    cudaStreamWaitEvent(s1, eA, 0);
    cudaStreamWaitEvent(s2, eA, 0);

    // s1: CSR build + layer-1 attention prep (all fp32-exact inputs)
    zero_k<<<(Nn + TPB - 1) / TPB, TPB, 0, s1>>>();
    count_k<<<egrid, TPB, 0, s1>>>(ei);
    scan_k<<<1, 1024, 0, s1>>>();
    scatter_k<<<egrid, TPB, 0, s1>>>(ei);
    precompute_vw<<<(DIN * 32 + TPB - 1) / TPB, TPB, 0, s1>>>(w1s, w1d, a1s, a1d, v1, DIN, C1);
    gemv_asd<<<wgrid, TPB, 0, s1>>>(x, v1, asd1, DIN);
    attn_k<<<wgrid, TPB, 0, s1>>>(asd1);
    cudaEventRecord(e1, s1);

    // s2: layer-2 folded attention vectors (weights only)
    precompute_vw<<<(F1 * 32 + TPB - 1) / TPB, TPB, 0, s2>>>(w2s, w2d, a2s, a2d, v2, F1, C2);
    cudaEventRecord(e2, s2);

    // main: round + gemm1
    round_all<<<rgrid, TPB, 0, m>>>(x, w1s, w2s, wf1);
    {
        dim3 g(F1 / 128, mgrid, 1);
        mma_gemm_k<<<g, 256, 0, m>>>(xtf, w1tf, xs1, Nn, F1, DIN, DIN);
    }
    cudaStreamWaitEvent(m, e1, 0);
    aggregate_k<C1><<<Nn, F1 / 4, 0, m>>>(xs1, b1, h1);   // h1 tf32-rounded

    // ---- fork B: gemv2/attn2 (s1) alongside gemm2 (main) ----
    cudaEventRecord(eB, m);
    cudaStreamWaitEvent(s1, eB, 0);
    cudaStreamWaitEvent(s1, e2, 0);
    gemv_asd<<<wgrid, TPB, 0, s1>>>(h1, v2, asd2, F1);
    attn_k<<<wgrid, TPB, 0, s1>>>(asd2);
    cudaEventRecord(e3, s1);

    {
        dim3 g(F2 / 128, mgrid, 1);
        mma_gemm_k<<<g, 256, 0, m>>>(h1, w2tf, xs2, Nn, F2, F1, F1);
    }
    cudaStreamWaitEvent(m, e3, 0);
    aggregate_k<C2><<<Nn, F2 / 4, 0, m>>>(xs2, b2, h2);   // h2 tf32-rounded

    // ---- MLP head: gemm3 split-K=4 into partials (reuse g_xs2), then reduce ----
    {
        dim3 g(HID / 128, mgrid, 4);                // 1 x 79 x 4 = 316 CTAs
        mma_gemm_k<<<g, 256, 0, m>>>(h2, wftf, xs2, Nn, HID, F2, F2 / 4);
    }
    reduce3_k<<<(Nn * HID + TPB - 1) / TPB, TPB, 0, m>>>(xs2, bf1, z);
    stats_k<<<128, HID, 0, m>>>();
    finalize_k<<<1, HID, 0, m>>>();
    head_k<<<wgrid, TPB, 0, m>>>(gamma, beta, wf2, bf2, out);
}